// round 5
// baseline (speedup 1.0000x reference)
#include <cuda_runtime.h>
#include <cstdint>
#include <math.h>

// ============================================================================
// Fused NeRF MLP (RadianceField) for base sm_100 target (no tcgen05).
// mma.sync.m16n8k8 tf32, persistent 256-thread CTAs, cp.async weight stream.
// ============================================================================

#define NTHREADS 256
#define MTILE    128

#define ACT_S    260                 // floats per row (mod 32 == 4 -> conflict-free frags)
#define XB_S     66                  // floats per row for x/d buffer
#define ACT_OFF  0                   // bytes
#define XB_OFF   (128 * ACT_S * 4)   // 133120
#define WB_OFF   (XB_OFF + 128 * XB_S * 4)   // 166912
#define WB_BYTES 32768               // 256 rows * 32 cols * 4B
#define SMEM_TOTAL (WB_OFF + 2 * WB_BYTES)   // 232448 == sm_100 opt-in cap

#define TOT_CHUNKS 89

struct Params { const float* p[32]; };

__constant__ int c_widx[13] = {2, 4, 6, 8, 10, 12, 14, 16, 20, 22, 24, 26, 28};
__constant__ int c_kact[13] = {63, 256, 256, 256, 256, 319, 256, 256, 256, 283, 128, 128, 128};
__constant__ int c_nch [13] = { 2,   8,   8,   8,   8,  10,   8,   8,   8,   9,   4,   4,   4};

// ----------------------------------------------------------------------------
__device__ __forceinline__ uint32_t smem_u32_of(const void* p) {
    uint32_t a;
    asm("{ .reg .u64 t; cvta.to.shared.u64 t, %1; cvt.u32.u64 %0, t; }" : "=r"(a) : "l"(p));
    return a;
}

__device__ __forceinline__ uint32_t cvt_tf32(float v) {
    uint32_t r;
    asm("cvt.rna.tf32.f32 %0, %1;" : "=r"(r) : "f"(v));
    return r;
}
__device__ __forceinline__ float rnd_tf32(float v) { return __uint_as_float(cvt_tf32(v)); }

__device__ __forceinline__ void cp_async16(uint32_t dst, const void* src) {
    asm volatile("cp.async.ca.shared.global [%0], [%1], 16;" :: "r"(dst), "l"(src));
}
__device__ __forceinline__ void cp_async4(uint32_t dst, const void* src, int srcsize) {
    asm volatile("cp.async.ca.shared.global [%0], [%1], 4, %2;"
                 :: "r"(dst), "l"(src), "r"(srcsize));
}
__device__ __forceinline__ void cp_commit() { asm volatile("cp.async.commit_group;"); }
template <int N> __device__ __forceinline__ void cp_wait() {
    asm volatile("cp.async.wait_group %0;" :: "n"(N));
}

__device__ __forceinline__ float lds_f32(uint32_t addr) {
    float f;
    asm("ld.shared.f32 %0, [%1];" : "=f"(f) : "r"(addr));
    return f;
}

__device__ __forceinline__ void mma_tf32(float c[4], uint32_t a0, uint32_t a1,
                                         uint32_t a2, uint32_t a3,
                                         uint32_t b0, uint32_t b1) {
    asm volatile(
        "mma.sync.aligned.m16n8k8.row.col.f32.tf32.tf32.f32 "
        "{%0,%1,%2,%3}, {%4,%5,%6,%7}, {%8,%9}, {%0,%1,%2,%3};"
        : "+f"(c[0]), "+f"(c[1]), "+f"(c[2]), "+f"(c[3])
        : "r"(a0), "r"(a1), "r"(a2), "r"(a3), "r"(b0), "r"(b1));
}

// Weight SMEM chunk addressing: raw [n][32] fp32 rows of 128B with 16B-granule
// XOR swizzle -> B-fragment scalar LDS is bank-conflict-free.
__device__ __forceinline__ uint32_t wb_addr(uint32_t wb_base, int n, int k) {
    return wb_base + (uint32_t)((n * 8 + ((k >> 2) ^ (n & 7))) * 16 + (k & 3) * 4);
}

// ----------------------------------------------------------------------------
// Issue one weight chunk (kk..kk+31 of W[N][K]) into buffer via cp.async.
// ----------------------------------------------------------------------------
__device__ __forceinline__ void issue_chunk(const float* __restrict__ W, int K, int kk,
                                            int N, uint32_t wb_base, int tid) {
    if ((K & 3) == 0) {
        // K=256/128: rows 16B aligned, chunk fully in-bounds
        const int iters = N >> 5;  // N*8 granules / 256 threads
        for (int i = 0; i < iters; i++) {
            int f4 = i * NTHREADS + tid;
            int n = f4 >> 3, k4 = f4 & 7;
            const float* src = W + (size_t)n * K + kk + k4 * 4;
            uint32_t dst = wb_base + (uint32_t)((n * 8 + (k4 ^ (n & 7))) * 16);
            cp_async16(dst, src);
        }
    } else {
        const int iters = N >> 3;  // N*32 elems / 256 threads
        for (int i = 0; i < iters; i++) {
            int f = i * NTHREADS + tid;
            int n = f >> 5, k = f & 31;
            int kg = kk + k;
            int ss = (kg < K) ? 4 : 0;
            int kc = (kg < K) ? kg : (K - 1);
            cp_async4(wb_addr(wb_base, n, k), W + (size_t)n * K + kc, ss);
        }
    }
    cp_commit();
}

// ----------------------------------------------------------------------------
// Compute one 32-k-col chunk into acc. NMT m-tiles starting at mt0.
// ----------------------------------------------------------------------------
template <int NMT>
__device__ __forceinline__ void compute_chunk(float acc[8][4][4],
                                              const float* __restrict__ Af, int S, int cb,
                                              uint32_t wb_base, int nb8, int lane, int mt0) {
#pragma unroll
    for (int k8 = 0; k8 < 4; k8++) {
        const int kin = k8 * 8 + (lane & 3);
        uint32_t bfr[8];
#pragma unroll
        for (int nt = 0; nt < 4; nt++) {
            int n = nb8 + nt * 8 + (lane >> 2);
            float f0 = lds_f32(wb_addr(wb_base, n, kin));
            float f1 = lds_f32(wb_addr(wb_base, n, kin + 4));
            bfr[nt * 2 + 0] = cvt_tf32(f0);
            bfr[nt * 2 + 1] = cvt_tf32(f1);
        }
        const int col = cb + k8 * 8 + (lane & 3);
#pragma unroll
        for (int mtl = 0; mtl < NMT; mtl++) {
            int row0 = (mt0 + mtl) * 16 + (lane >> 2);
            const float* ap = Af + (size_t)row0 * S + col;
            uint32_t a0 = __float_as_uint(ap[0]);
            uint32_t a2 = __float_as_uint(ap[4]);
            uint32_t a1 = __float_as_uint(ap[8 * S]);
            uint32_t a3 = __float_as_uint(ap[8 * S + 4]);
#pragma unroll
            for (int nt = 0; nt < 4; nt++)
                mma_tf32(acc[mtl][nt], a0, a1, a2, a3, bfr[nt * 2], bfr[nt * 2 + 1]);
        }
    }
}

template <int NMT>
__device__ __forceinline__ void zero_acc(float acc[8][4][4]) {
#pragma unroll
    for (int m = 0; m < NMT; m++)
#pragma unroll
        for (int n = 0; n < 4; n++)
#pragma unroll
            for (int q = 0; q < 4; q++) acc[m][n][q] = 0.0f;
}

// Epilogue: bias + (relu) + tf32-round, write to ACT.
template <int NMT>
__device__ __forceinline__ void epilogue(float acc[8][4][4], float* __restrict__ ACT,
                                         const float* __restrict__ bb, bool relu,
                                         int nb8, int lane, int mt0) {
#pragma unroll
    for (int mtl = 0; mtl < NMT; mtl++) {
        int row0 = (mt0 + mtl) * 16 + (lane >> 2);
#pragma unroll
        for (int nt = 0; nt < 4; nt++) {
            int col0 = nb8 + nt * 8 + 2 * (lane & 3);
            float2 bv = __ldg((const float2*)(bb + col0));
            float v0 = acc[mtl][nt][0] + bv.x;
            float v1 = acc[mtl][nt][1] + bv.y;
            float v2 = acc[mtl][nt][2] + bv.x;
            float v3 = acc[mtl][nt][3] + bv.y;
            if (relu) {
                v0 = fmaxf(v0, 0.0f); v1 = fmaxf(v1, 0.0f);
                v2 = fmaxf(v2, 0.0f); v3 = fmaxf(v3, 0.0f);
            }
            float2 lo = make_float2(rnd_tf32(v0), rnd_tf32(v1));
            float2 hi = make_float2(rnd_tf32(v2), rnd_tf32(v3));
            *(float2*)(ACT + (size_t)row0 * ACT_S + col0) = lo;
            *(float2*)(ACT + (size_t)(row0 + 8) * ACT_S + col0) = hi;
        }
    }
}

// ----------------------------------------------------------------------------
// Kernel
// ----------------------------------------------------------------------------
__global__ void __launch_bounds__(NTHREADS, 1)
nerf_fused_kernel(Params P, float* __restrict__ out, int ntiles, int Btot) {
    extern __shared__ __align__(16) float smf[];
    float* ACT = smf;                                  // [128][260]
    float* XB  = (float*)((char*)smf + XB_OFF);        // [128][66]
    const uint32_t sb = smem_u32_of(smf);
    const uint32_t wb0 = sb + WB_OFF;

    const int tid = threadIdx.x;
    const int w = tid >> 5;
    const int lane = tid & 31;

    const float* __restrict__ xin  = P.p[0];
    const float* __restrict__ ddir = P.p[1];
    const float* __restrict__ wsig = P.p[18];
    const float  bsig = __ldg(P.p[19]);
    const float* __restrict__ wrgb = P.p[30];
    const float* __restrict__ brgb = P.p[31];

    float acc[8][4][4];

    for (int tile = blockIdx.x; tile < ntiles; tile += gridDim.x) {
        __syncthreads();

        // ---- issue weight chunk 0 (layer 0) immediately, then load x
        issue_chunk(P.p[c_widx[0]], c_kact[0], 0, 256, wb0, tid);
        int gi = 1;            // chunks issued
        int ni_li = 0, ni_c = 1;  // coords of next chunk to issue

        // x -> XBUF cols 0..62 (tf32-rounded), col 63 = 0
        {
            const float* xs = xin + (size_t)tile * MTILE * 63;
#pragma unroll 4
            for (int i = 0; i < 32; i++) {
                int e = i * NTHREADS + tid;
                if (e < MTILE * 63) {
                    int r = e / 63, c = e - r * 63;
                    XB[r * XB_S + c] = rnd_tf32(__ldg(xs + e));
                }
            }
            if (tid < MTILE) XB[tid * XB_S + 63] = 0.0f;
        }

        int g = 0;  // global chunk counter this tile
        for (int li = 0; li < 13; li++) {
            const int K = c_kact[li];
            const int nch = c_nch[li];
            const int N = (li < 9) ? 256 : 128;
            const float* __restrict__ bb = P.p[c_widx[li] + 1];

            const int nb8 = (N == 256) ? (w * 32) : ((w & 3) * 32);
            const int mt0 = (N == 256) ? 0 : ((w >> 2) * 4);

            if (N == 256) zero_acc<8>(acc); else zero_acc<4>(acc);

            for (int c = 0; c < nch; c++) {
                // lookahead issue
                if (gi < TOT_CHUNKS) {
                    int nli = ni_li, nc = ni_c;
                    issue_chunk(P.p[c_widx[nli]], c_kact[nli], nc * 32,
                                (nli < 9) ? 256 : 128, wb0 + (gi & 1) * WB_BYTES, tid);
                    gi++;
                    if (nc + 1 < c_nch[nli]) ni_c = nc + 1; else { ni_li = nli + 1; ni_c = 0; }
                    cp_wait<1>();
                } else {
                    cp_wait<0>();
                }
                __syncthreads();

                // A source for this chunk
                const float* Af; int S, cb;
                if (li == 0)                { Af = XB;  S = XB_S;  cb = c * 32; }
                else if (li == 5 && c >= 8) { Af = XB;  S = XB_S;  cb = (c - 8) * 32; }
                else if (li == 9 && c == 8) { Af = XB;  S = XB_S;  cb = 0; }
                else                        { Af = ACT; S = ACT_S; cb = c * 32; }

                uint32_t wb = wb0 + (uint32_t)(g & 1) * WB_BYTES;
                if (N == 256) compute_chunk<8>(acc, Af, S, cb, wb, nb8, lane, mt0);
                else          compute_chunk<4>(acc, Af, S, cb, wb, nb8, lane, mt0);
                __syncthreads();
                g++;
            }

            // ---- epilogue: bias (+relu except layer 8), write ACT
            if (N == 256) epilogue<8>(acc, ACT, bb, li != 8, nb8, lane, mt0);
            else          epilogue<4>(acc, ACT, bb, li != 8, nb8, lane, mt0);
            __syncthreads();

            if (li == 7) {
                // sigma = softplus(h7 . wsig + bsig): 2 threads per row
                int r = tid >> 1, half = tid & 1;
                const float* hp = ACT + (size_t)r * ACT_S + half * 128;
                const float* wp = wsig + half * 128;
                float a = 0.0f;
#pragma unroll
                for (int i = 0; i < 32; i++) {
                    float4 h = *(const float4*)(hp + i * 4);
                    float4 wv = __ldg((const float4*)(wp + i * 4));
                    a += h.x * wv.x + h.y * wv.y + h.z * wv.z + h.w * wv.w;
                }
                a += __shfl_xor_sync(0xFFFFFFFFu, a, 1);
                if (!half) {
                    float z = a + bsig;
                    float sp = fmaxf(z, 0.0f) + log1pf(expf(-fabsf(z)));
                    out[(size_t)3 * Btot + (size_t)tile * MTILE + r] = sp;
                }
            }
            if (li == 5) {
                // d -> XBUF cols 0..26, zero 27..31 (x is dead now)
                const float* ds = ddir + (size_t)tile * MTILE * 27;
#pragma unroll 4
                for (int i = 0; i < 14; i++) {
                    int e = i * NTHREADS + tid;
                    if (e < MTILE * 27) {
                        int r = e / 27, c2 = e - r * 27;
                        XB[r * XB_S + c2] = rnd_tf32(__ldg(ds + e));
                    }
                }
                if (tid < MTILE) {
#pragma unroll
                    for (int c2 = 27; c2 < 32; c2++) XB[tid * XB_S + c2] = 0.0f;
                }
                __syncthreads();
            }
            if (li == 12) {
                // rgb = sigmoid(h12 @ Wrgb^T + brgb)
                if (tid < MTILE) {
                    const float* hp = ACT + (size_t)tid * ACT_S;
                    float a0 = 0.0f, a1 = 0.0f, a2 = 0.0f;
#pragma unroll
                    for (int i = 0; i < 32; i++) {
                        float4 h = *(const float4*)(hp + i * 4);
                        float4 w0 = __ldg((const float4*)(wrgb +   0 + i * 4));
                        float4 w1 = __ldg((const float4*)(wrgb + 128 + i * 4));
                        float4 w2 = __ldg((const float4*)(wrgb + 256 + i * 4));
                        a0 += h.x * w0.x + h.y * w0.y + h.z * w0.z + h.w * w0.w;
                        a1 += h.x * w1.x + h.y * w1.y + h.z * w1.z + h.w * w1.w;
                        a2 += h.x * w2.x + h.y * w2.y + h.z * w2.z + h.w * w2.w;
                    }
                    a0 = 1.0f / (1.0f + expf(-(a0 + __ldg(brgb + 0))));
                    a1 = 1.0f / (1.0f + expf(-(a1 + __ldg(brgb + 1))));
                    a2 = 1.0f / (1.0f + expf(-(a2 + __ldg(brgb + 2))));
                    float* orow = out + ((size_t)tile * MTILE + tid) * 3;
                    orow[0] = a0; orow[1] = a1; orow[2] = a2;
                }
            }
        }
    }
}

// ----------------------------------------------------------------------------
extern "C" void kernel_launch(void* const* d_in, const int* in_sizes, int n_in,
                              void* d_out, int out_size) {
    Params P;
    for (int i = 0; i < 32; i++) P.p[i] = (const float*)d_in[i];

    const int B = in_sizes[0] / 63;     // x is [B, 63]
    const int ntiles = B / MTILE;

    cudaFuncSetAttribute(nerf_fused_kernel,
                         cudaFuncAttributeMaxDynamicSharedMemorySize, SMEM_TOTAL);

    int nsm = 148;
    cudaDeviceGetAttribute(&nsm, cudaDevAttrMultiProcessorCount, 0);
    int grid = (nsm < ntiles) ? nsm : ntiles;

    nerf_fused_kernel<<<grid, NTHREADS, SMEM_TOTAL>>>(P, (float*)d_out, ntiles, B);
}